// round 14
// baseline (speedup 1.0000x reference)
#include <cuda_runtime.h>
#include <math.h>

#define NFFT 4096
#define DDIM 256
#define HDIM 64
#define NB4  4   // BATCH/2 packed complex batches

typedef unsigned long long u64;

// ---------------- device scratch ----------------
__device__ float2 g_twp[3 * 7 * 512];         // per-(stage,k,thread) twiddles, fwd
__device__ float2 g_Kf[DDIM * NFFT];          // Hermitian (kernel+D) spectrum / N
__device__ float2 g_zT[NB4 * DDIM * NFFT];    // packed transposed signals

// ---------------- f32x2 packed helpers ----------------
__device__ __forceinline__ u64 pk2(float a, float b) {
    u64 r; asm("mov.b64 %0,{%1,%2};" : "=l"(r) : "f"(a), "f"(b)); return r;
}
__device__ __forceinline__ void upk2(u64 v, float& a, float& b) {
    asm("mov.b64 {%0,%1},%2;" : "=f"(a), "=f"(b) : "l"(v));
}
__device__ __forceinline__ u64 fma2(u64 a, u64 b, u64 c) {
    u64 d; asm("fma.rn.f32x2 %0,%1,%2,%3;" : "=l"(d) : "l"(a), "l"(b), "l"(c)); return d;
}
__device__ __forceinline__ u64 add2(u64 a, u64 b) {
    u64 d; asm("add.rn.f32x2 %0,%1,%2;" : "=l"(d) : "l"(a), "l"(b)); return d;
}
__device__ __forceinline__ u64 mul2(u64 a, u64 b) {
    u64 d; asm("mul.rn.f32x2 %0,%1,%2;" : "=l"(d) : "l"(a), "l"(b)); return d;
}
__device__ __forceinline__ u64 swp(u64 a) {
    float x, y; upk2(a, x, y); return pk2(y, x);
}

// =====================================================================
// Fused kernel A: blocks [0, 1024)    -> pair-reduced Cauchy spectrum (+ D/N)
//                                        2 points/thread, packed den chain
//                 blocks [1024, 3072) -> transpose (B,L,D)->(B4,D,L), MLP=4
//                 blocks [3072, 3114) -> fft twiddle tables (NEXT launch)
// =====================================================================
__global__ __launch_bounds__(256, 4) void kf_t1_kernel(
    const float* __restrict__ x,
    const float2* __restrict__ lam, const float2* __restrict__ P,
    const float2* __restrict__ B,   const float2* __restrict__ C,
    const float* __restrict__ log_delta, const float* __restrict__ Dp)
{
    __shared__ float2 slam[HDIM];
    __shared__ float4 tW0[HDIM];              // (w00x, w00y, w01x, w01y)
    __shared__ float4 tW1[HDIM];              // (w10x, w10y, w11, 0)
    __shared__ int    sbi[HDIM];
    __shared__ unsigned sLm[2], sRm[2];
    __shared__ int    pA[32], pB[32], realIdx[HDIM];
    __shared__ float4 sMN2[32];               // (m, m, n, n)
    __shared__ float4 sE0a[32];               // (e0_00,e0_00,e0_01,e0_01)
    __shared__ float4 sE1a[32];               // (e1_00,e1_00,e1_01,e1_01)
    __shared__ float4 sE0b[32];               // (e0_10,e0_10,e0_11,e0_11)
    __shared__ float4 sE1b[32];               // (e1_10,e1_10,e1_11,e1_11)
    __shared__ float2 tile[64][33];

    int tid = threadIdx.x;

    if (blockIdx.x < 1024) {
        // -------- kf path: d in [0,256), part in [0,4), 2 points/thread -----
        int d    = blockIdx.x >> 2;
        int part = blockIdx.x & 3;

        if (tid < HDIM) slam[tid] = lam[tid];
        __syncthreads();
        if (tid < HDIM) {
            float2 L = slam[tid];
            float best = 3.4e38f; int bi = tid;
            #pragma unroll 8
            for (int j = 0; j < HDIM; ++j) {
                float2 M = slam[j];
                float dx = M.x - L.x, dy = M.y + L.y;   // |lam_j - conj(lam_h)|^2
                float e = dx * dx + dy * dy;
                if (e < best) { best = e; bi = j; }
            }
            sbi[tid] = bi;
            float2 c  = C[(d << 6) + tid];
            float2 c2 = C[(d << 6) | bi];
            float chx = 0.5f * (c.x + c2.x);
            float chy = 0.5f * (c.y - c2.y);           // Chat = (C_h + conj(C_hbar))/2
            float2 b = B[(d << 6) + tid];
            float2 p = P[tid];
            float w00x = chx * b.x - chy * b.y, w00y = chx * b.y + chy * b.x;
            float w01x = chx * p.x - chy * p.y, w01y = chx * p.y + chy * p.x;
            float w10x = p.x * b.x + p.y * b.y, w10y = p.x * b.y - p.y * b.x;
            float w11  = p.x * p.x + p.y * p.y;
            tW0[tid] = make_float4(w00x, w00y, w01x, w01y);
            tW1[tid] = make_float4(w10x, w10y, w11, 0.0f);
        }
        __syncthreads();
        // ballots: warps 0,1 fully cover tid<64
        if (tid < HDIM) {
            int bi = sbi[tid];
            unsigned lm = __ballot_sync(0xffffffffu, bi > tid);
            unsigned rm = __ballot_sync(0xffffffffu, bi == tid);
            if ((tid & 31) == 0) { sLm[tid >> 5] = lm; sRm[tid >> 5] = rm; }
        }
        __syncthreads();
        if (tid < HDIM) {
            int lane = tid & 31, w = tid >> 5;
            int bi = sbi[tid];
            unsigned below = (1u << lane) - 1u;
            if (bi > tid) {                    // conj-pair lead
                int slot = __popc(sLm[w] & below) + (w ? __popc(sLm[0]) : 0);
                pA[slot] = tid; pB[slot] = bi;
            } else if (bi == tid) {            // real pole: record rank
                int r = __popc(sRm[w] & below) + (w ? __popc(sRm[0]) : 0);
                realIdx[r] = tid;
            }
        }
        __syncthreads();
        if (tid < HDIM) {
            int bi = sbi[tid];
            if (bi == tid) {
                int lane = tid & 31, w = tid >> 5;
                int r = __popc(sRm[w] & ((1u << lane) - 1u)) + (w ? __popc(sRm[0]) : 0);
                if (!(r & 1)) {                // even-rank real creates the slot
                    int nLead = __popc(sLm[0]) + __popc(sLm[1]);
                    int nReal = __popc(sRm[0]) + __popc(sRm[1]);
                    int slot = nLead + (r >> 1);
                    pA[slot] = tid;
                    pB[slot] = (r + 1 < nReal) ? realIdx[r + 1] : -1;
                }
            }
        }
        __syncthreads();
        // slot parameters
        if (tid < 32) {
            int h1 = pA[tid], h2r = pB[tid];
            int h2 = (h2r >= 0) ? h2r : h1;
            float zf = (h2r >= 0) ? 1.0f : 0.0f;
            float2 u1 = slam[h1], u2 = slam[h2];
            float m = u1.x * u2.x - u1.y * u2.y;
            float n = u1.x + u2.x;
            sMN2[tid] = make_float4(m, m, n, n);
            float4 a1 = tW0[h1], a2 = tW0[h2];
            float4 b1 = tW1[h1], b2 = tW1[h2];
            float e1_00 = a1.x + zf * a2.x;
            float e0_00 = -(a1.x * u2.x - a1.y * u2.y + zf * (a2.x * u1.x - a2.y * u1.y));
            float e1_01 = a1.z + zf * a2.z;
            float e0_01 = -(a1.z * u2.x - a1.w * u2.y + zf * (a2.z * u1.x - a2.w * u1.y));
            float e1_10 = b1.x + zf * b2.x;
            float e0_10 = -(b1.x * u2.x - b1.y * u2.y + zf * (b2.x * u1.x - b2.y * u1.y));
            float e1_11 = b1.z + zf * b2.z;
            float e0_11 = -(b1.z * u2.x + zf * b2.z * u1.x);
            sE0a[tid] = make_float4(e0_00, e0_00, e0_01, e0_01);
            sE1a[tid] = make_float4(e1_00, e1_00, e1_01, e1_01);
            sE0b[tid] = make_float4(e0_10, e0_10, e0_11, e0_11);
            sE1b[tid] = make_float4(e1_10, e1_10, e1_11, e1_11);
        }
        __syncthreads();

        float delta = __expf(log_delta[d]);
        const float sc = 1.0f / (float)NFFT;       // fold 1/N of inverse FFT
        float dsc = Dp[d] * sc;                    // D*x folded: Kf += D/N at every bin

        // Nyquist bin (z = -1): at = 0.5*delta*sum_h Re(w00) = 0.5*delta*sum_s e1_00
        if (part == 0 && tid == 0) {
            float s = 0.0f;
            #pragma unroll
            for (int q = 0; q < 32; ++q) s += sE1a[q].x;
            g_Kf[(d << 12) + 2048] = make_float2(0.5f * delta * s * sc + dsc, 0.0f);
        }

        // Two points per thread: l0p = part*512 + tid, l1p = l0p + 256
        int l0p = part * 512 + tid;
        int l1p = l0p + 256;
        float mtwo = __fdividef(-2.0f, delta);
        float s0_, c0_, s1_, c1_;
        sincospif((float)l0p * (1.0f / 4096.0f), &s0_, &c0_);
        sincospif((float)l1p * (1.0f / 4096.0f), &s1_, &c1_);
        float th0 = __fdividef(s0_, c0_);
        float th1 = __fdividef(s1_, c1_);
        float G0 = th0 * mtwo, G1 = th1 * mtwo;
        u64 G01  = pk2(G0, G1);
        u64 nGsq = pk2(-G0 * G0, -G1 * G1);

        u64 P00a = 0ull, P01a = 0ull, P10a = 0ull, P11a = 0ull;
        u64 Q00a = 0ull, Q01a = 0ull, Q10a = 0ull, Q11a = 0ull;
        u64 P00b = 0ull, P01b = 0ull, P10b = 0ull, P11b = 0ull;
        u64 Q00b = 0ull, Q01b = 0ull, Q10b = 0ull, Q11b = 0ull;
        const ulonglong2* pMN  = (const ulonglong2*)sMN2;
        const ulonglong2* pE0a = (const ulonglong2*)sE0a;
        const ulonglong2* pE1a = (const ulonglong2*)sE1a;
        const ulonglong2* pE0b = (const ulonglong2*)sE0b;
        const ulonglong2* pE1b = (const ulonglong2*)sE1b;
        #pragma unroll 4
        for (int s = 0; s < 32; ++s) {
            ulonglong2 MN = pMN[s];                 // (m,m),(n,n)
            // packed denominator chain for both points
            u64 dx2  = add2(MN.x, nGsq);            // (dx0, dx1)
            u64 dyn2 = mul2(MN.y, G01);             // (dyn0, dyn1)
            u64 den2 = fma2(dx2, dx2, mul2(dyn2, dyn2));
            float den0, den1; upk2(den2, den0, den1);
            float im0 = __fdividef(1.0f, den0);
            float im1 = __fdividef(1.0f, den1);
            float dx0, dx1, dyn0, dyn1;
            upk2(dx2, dx0, dx1); upk2(dyn2, dyn0, dyn1);
            u64 t0 = pk2(dx0 * im0, dyn0 * im0);
            u64 t1 = pk2(dx1 * im1, dyn1 * im1);
            ulonglong2 E0A = pE0a[s];
            ulonglong2 E1A = pE1a[s];
            ulonglong2 E0B = pE0b[s];
            ulonglong2 E1B = pE1b[s];
            P00a = fma2(E0A.x, t0, P00a); Q00a = fma2(E1A.x, t0, Q00a);
            P01a = fma2(E0A.y, t0, P01a); Q01a = fma2(E1A.y, t0, Q01a);
            P10a = fma2(E0B.x, t0, P10a); Q10a = fma2(E1B.x, t0, Q10a);
            P11a = fma2(E0B.y, t0, P11a); Q11a = fma2(E1B.y, t0, Q11a);
            P00b = fma2(E0A.x, t1, P00b); Q00b = fma2(E1A.x, t1, Q00b);
            P01b = fma2(E0A.y, t1, P01b); Q01b = fma2(E1A.y, t1, Q01b);
            P10b = fma2(E0B.x, t1, P10b); Q10b = fma2(E1B.x, t1, Q10b);
            P11b = fma2(E0B.y, t1, P11b); Q11b = fma2(E1B.y, t1, Q11b);
        }

        // epilogue per point: s = P + iG*Q, Woodbury, 2/u = 1 - i*th, scale
        #pragma unroll
        for (int k = 0; k < 2; ++k) {
            float G  = k ? G1 : G0;
            float th = k ? th1 : th0;
            int   l  = k ? l1p : l0p;
            u64 uP00 = k ? P00b : P00a, uQ00 = k ? Q00b : Q00a;
            u64 uP01 = k ? P01b : P01a, uQ01 = k ? Q01b : Q01a;
            u64 uP10 = k ? P10b : P10a, uQ10 = k ? Q10b : Q10a;
            u64 uP11 = k ? P11b : P11a, uQ11 = k ? Q11b : Q11a;
            float px, py, qx, qy;
            upk2(uP00, px, py); upk2(uQ00, qx, qy);
            float s00x = px - G * qy, s00y = py + G * qx;
            upk2(uP01, px, py); upk2(uQ01, qx, qy);
            float s01x = px - G * qy, s01y = py + G * qx;
            upk2(uP10, px, py); upk2(uQ10, qx, qy);
            float s10x = px - G * qy, s10y = py + G * qx;
            upk2(uP11, px, py); upk2(uQ11, qx, qy);
            float s11x = px - G * qy, s11y = py + G * qx;

            float nx  = s01x * s10x - s01y * s10y;
            float ny  = s01x * s10y + s01y * s10x;
            float dnx = 1.0f + s11x, dny = s11y;
            float ddi = __fdividef(1.0f, dnx * dnx + dny * dny);
            float cx  = (nx * dnx + ny * dny) * ddi;
            float cy  = (ny * dnx - nx * dny) * ddi;
            float k0x = s00x - cx, k0y = s00y - cy;
            float ax = k0x + th * k0y;
            float ay = k0y - th * k0x;
            ax = ax * sc + dsc; ay *= sc;
            if (l == 0) ay = 0.0f;
            g_Kf[(d << 12) + l] = make_float2(ax, ay);
            if (l > 0)
                g_Kf[(d << 12) + (NFFT - l)] = make_float2(ax, -ay);
        }
    } else if (blockIdx.x < 3072) {
        // -------- t1 path: 32d x 64l tiles, MLP=4 --------
        int m  = blockIdx.x - 1024;                // [0, 2048)
        int b4 = m >> 9;
        int lblk = (m >> 3) & 63;
        int dblk = m & 7;
        int d0 = dblk << 5, l0 = lblk << 6;
        const float4* x4 = (const float4*)x;
        float4 A[2], Bv[2];
        #pragma unroll
        for (int u = 0; u < 2; ++u) {
            int mm = tid + (u << 8);               // [0, 512)
            int l = mm >> 3, d4 = mm & 7;
            int base0 = ((b4 * NFFT) + l0 + l) * (DDIM / 4) + (d0 >> 2) + d4;
            A[u]  = x4[base0];
            Bv[u] = x4[base0 + 4 * NFFT * (DDIM / 4)];
        }
        #pragma unroll
        for (int u = 0; u < 2; ++u) {
            int mm = tid + (u << 8);
            int l = mm >> 3, d4 = mm & 7;
            tile[l][4 * d4 + 0] = make_float2(A[u].x, Bv[u].x);
            tile[l][4 * d4 + 1] = make_float2(A[u].y, Bv[u].y);
            tile[l][4 * d4 + 2] = make_float2(A[u].z, Bv[u].z);
            tile[l][4 * d4 + 3] = make_float2(A[u].w, Bv[u].w);
        }
        __syncthreads();
        float4* zT4 = (float4*)g_zT;
        #pragma unroll
        for (int u = 0; u < 4; ++u) {
            int mm = tid + (u << 8);               // [0, 1024)
            int dd = mm >> 5, lp = mm & 31;
            float2 t0 = tile[2 * lp][dd];
            float2 t1 = tile[2 * lp + 1][dd];
            zT4[(((b4 * DDIM) + d0 + dd) * NFFT + l0 + 2 * lp) >> 1]
                = make_float4(t0.x, t0.y, t1.x, t1.y);
        }
    } else {
        // -------- fft twiddle tables (used by the NEXT launch only) --------
        // layout: g_twp[st*3584 + (k-1)*512 + i] = e^{-2*pi*i*(k*ps)/N},
        // ps = (i >> (3*st)) << (3*st), st in {0,1,2}, k in [1,8)
        int e = (blockIdx.x - 3072) * 256 + tid;    // [0, 10752)
        int st = e / 3584;
        int r  = e - st * 3584;
        int k  = (r >> 9) + 1;
        int i  = r & 511;
        int tsh = 3 * st;
        int ps = (i >> tsh) << tsh;
        double ang = -6.283185307179586476925286766559 * (double)(k * ps) / (double)NFFT;
        g_twp[e] = make_float2((float)cos(ang), (float)sin(ang));
    }
}

// ---------------- radix-8 Stockham FFT, packed f32x2 butterflies ----------
// cmul by w (DIR>0) or conj(w) (DIR<0) on packed value
template<int DIR>
__device__ __forceinline__ u64 cmul_dir(u64 a, float2 w) {
    float x, y; upk2(a, x, y);
    if (DIR > 0) return pk2(x * w.x - y * w.y, x * w.y + y * w.x);
    else         return pk2(x * w.x + y * w.y, y * w.x - x * w.y);
}
__device__ __forceinline__ u64 cmul_s(u64 a, float2 w) {
    float x, y; upk2(a, x, y);
    return pk2(x * w.x - y * w.y, x * w.y + y * w.x);
}
#define SWZ(m) ((m) ^ (((m) >> 4) & 7))

// Packed radix-8 butterfly (verified lane-by-lane vs scalar form)
template<int DIR>
__device__ __forceinline__ void bfly8(u64 a[8]) {
    const float S2 = 0.70710678118654752440f;
    const u64 NEG1 = pk2(-1.0f, -1.0f);
    const u64 S2S2 = pk2(S2, S2);
    const u64 J    = (DIR > 0) ? pk2(1.0f, -1.0f) : pk2(-1.0f, 1.0f);
    u64 b0 = add2(a[0], a[4]), c0 = fma2(a[4], NEG1, a[0]);
    u64 b1 = add2(a[1], a[5]), c1 = fma2(a[5], NEG1, a[1]);
    u64 b2 = add2(a[2], a[6]), c2 = fma2(a[6], NEG1, a[2]);
    u64 b3 = add2(a[3], a[7]), c3 = fma2(a[7], NEG1, a[3]);
    u64 tc1 = mul2(fma2(swp(c1), J, c1), S2S2);
    u64 tc2 = mul2(swp(c2), J);
    u64 tc3 = mul2(fma2(c3, NEG1, mul2(swp(c3), J)), S2S2);
    u64 p0 = add2(b0, b2), p1 = fma2(b2, NEG1, b0);
    u64 p2 = add2(b1, b3), p3 = fma2(b3, NEG1, b1);
    u64 q0 = add2(c0, tc2), q1 = fma2(tc2, NEG1, c0);
    u64 q2 = add2(tc1, tc3), q3 = fma2(tc3, NEG1, tc1);
    u64 jp3 = mul2(swp(p3), J);
    u64 jq3 = mul2(swp(q3), J);
    a[0] = add2(p0, p2);  a[4] = fma2(p2, NEG1, p0);
    a[2] = add2(p1, jp3); a[6] = fma2(jp3, NEG1, p1);
    a[1] = add2(q0, q2);  a[5] = fma2(q2, NEG1, q0);
    a[3] = add2(q1, jq3); a[7] = fma2(jq3, NEG1, q1);
}

// twiddles from precomputed table: g_twp[ST*3584 + (k-1)*512 + i]
template<int DIR, int TSH, int ST>
__device__ __forceinline__ void stage_tw_store(u64* dst, u64 a[8], int i) {
    const int s = 1 << TSH;
    int ps = (i >> TSH) << TSH;
    if (TSH < 9) {
        const float2* wp = g_twp + ST * 3584 + i;
        #pragma unroll
        for (int k = 1; k < 8; ++k)
            a[k] = cmul_dir<DIR>(a[k], __ldg(&wp[(k - 1) * 512]));
    }
    int base = (i & (s - 1)) + (ps << 3);
    #pragma unroll
    for (int k = 0; k < 8; ++k) dst[SWZ(base + (k << TSH))] = a[k];
}

__global__ __launch_bounds__(512, 2) void fft_conv8_kernel() {
    extern __shared__ u64 sm64[];
    u64* S0 = sm64;
    u64* S1 = sm64 + NFFT;
    int d  = blockIdx.x & (DDIM - 1);
    int i  = threadIdx.x;
    u64* sig = (u64*)g_zT + (size_t)blockIdx.x * NFFT;
    u64 a[8];

    // ---- forward ----
    #pragma unroll
    for (int j = 0; j < 8; ++j) a[j] = sig[i + j * 512];
    bfly8<1>(a); stage_tw_store<1, 0, 0>(S0, a, i);
    __syncthreads();
    #pragma unroll
    for (int j = 0; j < 8; ++j) a[j] = S0[SWZ(i + j * 512)];
    bfly8<1>(a); stage_tw_store<1, 3, 1>(S1, a, i);
    __syncthreads();
    #pragma unroll
    for (int j = 0; j < 8; ++j) a[j] = S1[SWZ(i + j * 512)];
    bfly8<1>(a); stage_tw_store<1, 6, 2>(S0, a, i);
    __syncthreads();
    #pragma unroll
    for (int j = 0; j < 8; ++j) a[j] = S0[SWZ(i + j * 512)];
    bfly8<1>(a);
    // F3 (TSH=9): no twiddles; a[j] IS natural-order bin (i + j*512).
    {
        const float2* kf = g_Kf + (d << 12);
        #pragma unroll
        for (int j = 0; j < 8; ++j) a[j] = cmul_s(a[j], __ldg(&kf[i + j * 512]));
    }
    // ---- inverse ----
    bfly8<-1>(a); stage_tw_store<-1, 0, 0>(S1, a, i);
    __syncthreads();
    #pragma unroll
    for (int j = 0; j < 8; ++j) a[j] = S1[SWZ(i + j * 512)];
    bfly8<-1>(a); stage_tw_store<-1, 3, 1>(S0, a, i);
    __syncthreads();
    #pragma unroll
    for (int j = 0; j < 8; ++j) a[j] = S0[SWZ(i + j * 512)];
    bfly8<-1>(a); stage_tw_store<-1, 6, 2>(S1, a, i);
    __syncthreads();
    #pragma unroll
    for (int j = 0; j < 8; ++j) a[j] = S1[SWZ(i + j * 512)];
    bfly8<-1>(a);
    #pragma unroll
    for (int k = 0; k < 8; ++k) sig[i + k * 512] = a[k];
}

// ---------------- untranspose + split Re/Im (32d x 64l tiles, MLP=4) --------
__global__ __launch_bounds__(256) void t2_kernel(float* __restrict__ y) {
    __shared__ float2 tile[32][65];
    int b4 = blockIdx.z;
    int d0 = blockIdx.x << 5;
    int l0 = blockIdx.y << 6;
    int tid = threadIdx.x;
    const float4* zT4 = (const float4*)g_zT;
    #pragma unroll
    for (int u = 0; u < 4; ++u) {
        int m = tid + (u << 8);
        int dd = m >> 5, lp = m & 31;
        float4 v = zT4[(((b4 * DDIM) + d0 + dd) * NFFT + l0 + 2 * lp) >> 1];
        tile[dd][2 * lp]     = make_float2(v.x, v.y);
        tile[dd][2 * lp + 1] = make_float2(v.z, v.w);
    }
    __syncthreads();
    float4* y4 = (float4*)y;
    #pragma unroll
    for (int u = 0; u < 4; ++u) {
        int m = tid + (u << 8);
        int k = m & 7, l = (m >> 3) & 63;
        int plane = m >> 9;                        // u<2 -> 0 (Re), u>=2 -> 1 (Im)
        float2 t0 = tile[4 * k + 0][l];
        float2 t1 = tile[4 * k + 1][l];
        float2 t2 = tile[4 * k + 2][l];
        float2 t3 = tile[4 * k + 3][l];
        int row = ((b4 + plane * 4) * NFFT + l0 + l) * (DDIM / 4) + (d0 >> 2) + k;
        y4[row] = plane ? make_float4(t0.y, t1.y, t2.y, t3.y)
                        : make_float4(t0.x, t1.x, t2.x, t3.x);
    }
}

// ---------------- launcher ----------------
extern "C" void kernel_launch(void* const* d_in, const int* in_sizes, int n_in,
                              void* d_out, int out_size) {
    const float*  x   = (const float*)d_in[0];
    const float2* lam = (const float2*)d_in[1];
    const float2* P   = (const float2*)d_in[2];
    const float2* B   = (const float2*)d_in[3];
    const float2* C   = (const float2*)d_in[4];
    const float*  Dp  = (const float*)d_in[5];
    const float*  ld  = (const float*)d_in[6];
    float* y = (float*)d_out;

    cudaFuncSetAttribute(fft_conv8_kernel,
                         cudaFuncAttributeMaxDynamicSharedMemorySize,
                         2 * NFFT * sizeof(u64));

    kf_t1_kernel<<<1024 + 2048 + 42, 256>>>(x, lam, P, B, C, ld, Dp);
    fft_conv8_kernel<<<NB4 * DDIM, 512, 2 * NFFT * sizeof(u64)>>>();
    t2_kernel<<<dim3(DDIM / 32, NFFT / 64, NB4), dim3(256)>>>(y);
}

// round 15
// speedup vs baseline: 1.1782x; 1.1782x over previous
#include <cuda_runtime.h>
#include <math.h>

#define NFFT 4096
#define DDIM 256
#define HDIM 64
#define NB4  4   // BATCH/2 packed complex batches

typedef unsigned long long u64;

// ---------------- device scratch ----------------
__device__ float2 g_tw[NFFT];                 // e^{-2*pi*i*k/N}
__device__ float2 g_Kf[DDIM * NFFT];          // Hermitian (kernel+D) spectrum / N
__device__ float2 g_zT[NB4 * DDIM * NFFT];    // packed transposed signals

// ---------------- f32x2 packed helpers ----------------
__device__ __forceinline__ u64 pk2(float a, float b) {
    u64 r; asm("mov.b64 %0,{%1,%2};" : "=l"(r) : "f"(a), "f"(b)); return r;
}
__device__ __forceinline__ void upk2(u64 v, float& a, float& b) {
    asm("mov.b64 {%0,%1},%2;" : "=f"(a), "=f"(b) : "l"(v));
}
__device__ __forceinline__ u64 fma2(u64 a, u64 b, u64 c) {
    u64 d; asm("fma.rn.f32x2 %0,%1,%2,%3;" : "=l"(d) : "l"(a), "l"(b), "l"(c)); return d;
}
__device__ __forceinline__ u64 add2(u64 a, u64 b) {
    u64 d; asm("add.rn.f32x2 %0,%1,%2;" : "=l"(d) : "l"(a), "l"(b)); return d;
}
__device__ __forceinline__ u64 mul2(u64 a, u64 b) {
    u64 d; asm("mul.rn.f32x2 %0,%1,%2;" : "=l"(d) : "l"(a), "l"(b)); return d;
}
__device__ __forceinline__ u64 swp(u64 a) {
    float x, y; upk2(a, x, y); return pk2(y, x);
}

// =====================================================================
// Fused kernel A: blocks [0, 1024)    -> pair-reduced Cauchy spectrum (+ D/N)
//                                        2 points/thread, G factored out
//                 blocks [1024, 3072) -> transpose (B,L,D)->(B4,D,L), MLP=4
//                 blocks [3072, 3088) -> twiddle table (consumed by NEXT launch)
// =====================================================================
__global__ __launch_bounds__(256, 4) void kf_t1_kernel(
    const float* __restrict__ x,
    const float2* __restrict__ lam, const float2* __restrict__ P,
    const float2* __restrict__ B,   const float2* __restrict__ C,
    const float* __restrict__ log_delta, const float* __restrict__ Dp)
{
    __shared__ float2 slam[HDIM];
    __shared__ float4 tW0[HDIM];              // (w00x, w00y, w01x, w01y)
    __shared__ float4 tW1[HDIM];              // (w10x, w10y, w11, 0)
    __shared__ int    sbi[HDIM];
    __shared__ unsigned sLm[2], sRm[2];
    __shared__ int    pA[32], pB[32], realIdx[HDIM];
    __shared__ float2 sMN[32];                // (m, n)
    __shared__ float4 sE0a[32];               // (e0_00,e0_00,e0_01,e0_01)
    __shared__ float4 sE1a[32];               // (e1_00,e1_00,e1_01,e1_01)
    __shared__ float4 sE0b[32];               // (e0_10,e0_10,e0_11,e0_11)
    __shared__ float4 sE1b[32];               // (e1_10,e1_10,e1_11,e1_11)
    __shared__ float2 tile[64][33];

    int tid = threadIdx.x;

    if (blockIdx.x < 1024) {
        // -------- kf path: d in [0,256), part in [0,4), 2 points/thread -----
        int d    = blockIdx.x >> 2;
        int part = blockIdx.x & 3;

        if (tid < HDIM) slam[tid] = lam[tid];
        __syncthreads();
        if (tid < HDIM) {
            float2 L = slam[tid];
            float best = 3.4e38f; int bi = tid;
            #pragma unroll 8
            for (int j = 0; j < HDIM; ++j) {
                float2 M = slam[j];
                float dx = M.x - L.x, dy = M.y + L.y;   // |lam_j - conj(lam_h)|^2
                float e = dx * dx + dy * dy;
                if (e < best) { best = e; bi = j; }
            }
            sbi[tid] = bi;
            float2 c  = C[(d << 6) + tid];
            float2 c2 = C[(d << 6) | bi];
            float chx = 0.5f * (c.x + c2.x);
            float chy = 0.5f * (c.y - c2.y);           // Chat = (C_h + conj(C_hbar))/2
            float2 b = B[(d << 6) + tid];
            float2 p = P[tid];
            float w00x = chx * b.x - chy * b.y, w00y = chx * b.y + chy * b.x;
            float w01x = chx * p.x - chy * p.y, w01y = chx * p.y + chy * p.x;
            float w10x = p.x * b.x + p.y * b.y, w10y = p.x * b.y - p.y * b.x;
            float w11  = p.x * p.x + p.y * p.y;
            tW0[tid] = make_float4(w00x, w00y, w01x, w01y);
            tW1[tid] = make_float4(w10x, w10y, w11, 0.0f);
        }
        __syncthreads();
        // ballots: warps 0,1 fully cover tid<64
        if (tid < HDIM) {
            int bi = sbi[tid];
            unsigned lm = __ballot_sync(0xffffffffu, bi > tid);
            unsigned rm = __ballot_sync(0xffffffffu, bi == tid);
            if ((tid & 31) == 0) { sLm[tid >> 5] = lm; sRm[tid >> 5] = rm; }
        }
        __syncthreads();
        if (tid < HDIM) {
            int lane = tid & 31, w = tid >> 5;
            int bi = sbi[tid];
            unsigned below = (1u << lane) - 1u;
            if (bi > tid) {                    // conj-pair lead
                int slot = __popc(sLm[w] & below) + (w ? __popc(sLm[0]) : 0);
                pA[slot] = tid; pB[slot] = bi;
            } else if (bi == tid) {            // real pole: record rank
                int r = __popc(sRm[w] & below) + (w ? __popc(sRm[0]) : 0);
                realIdx[r] = tid;
            }
        }
        __syncthreads();
        if (tid < HDIM) {
            int bi = sbi[tid];
            if (bi == tid) {
                int lane = tid & 31, w = tid >> 5;
                int r = __popc(sRm[w] & ((1u << lane) - 1u)) + (w ? __popc(sRm[0]) : 0);
                if (!(r & 1)) {                // even-rank real creates the slot
                    int nLead = __popc(sLm[0]) + __popc(sLm[1]);
                    int nReal = __popc(sRm[0]) + __popc(sRm[1]);
                    int slot = nLead + (r >> 1);
                    pA[slot] = tid;
                    pB[slot] = (r + 1 < nReal) ? realIdx[r + 1] : -1;
                }
            }
        }
        __syncthreads();
        // slot parameters
        if (tid < 32) {
            int h1 = pA[tid], h2r = pB[tid];
            int h2 = (h2r >= 0) ? h2r : h1;
            float zf = (h2r >= 0) ? 1.0f : 0.0f;
            float2 u1 = slam[h1], u2 = slam[h2];
            float m = u1.x * u2.x - u1.y * u2.y;
            float n = u1.x + u2.x;
            sMN[tid] = make_float2(m, n);
            float4 a1 = tW0[h1], a2 = tW0[h2];
            float4 b1 = tW1[h1], b2 = tW1[h2];
            float e1_00 = a1.x + zf * a2.x;
            float e0_00 = -(a1.x * u2.x - a1.y * u2.y + zf * (a2.x * u1.x - a2.y * u1.y));
            float e1_01 = a1.z + zf * a2.z;
            float e0_01 = -(a1.z * u2.x - a1.w * u2.y + zf * (a2.z * u1.x - a2.w * u1.y));
            float e1_10 = b1.x + zf * b2.x;
            float e0_10 = -(b1.x * u2.x - b1.y * u2.y + zf * (b2.x * u1.x - b2.y * u1.y));
            float e1_11 = b1.z + zf * b2.z;
            float e0_11 = -(b1.z * u2.x + zf * b2.z * u1.x);
            sE0a[tid] = make_float4(e0_00, e0_00, e0_01, e0_01);
            sE1a[tid] = make_float4(e1_00, e1_00, e1_01, e1_01);
            sE0b[tid] = make_float4(e0_10, e0_10, e0_11, e0_11);
            sE1b[tid] = make_float4(e1_10, e1_10, e1_11, e1_11);
        }
        __syncthreads();

        float delta = __expf(log_delta[d]);
        const float sc = 1.0f / (float)NFFT;       // fold 1/N of inverse FFT
        float dsc = Dp[d] * sc;                    // D*x folded: Kf += D/N at every bin

        // Nyquist bin (z = -1): at = 0.5*delta*sum_h Re(w00) = 0.5*delta*sum_s e1_00
        if (part == 0 && tid == 0) {
            float s = 0.0f;
            #pragma unroll
            for (int q = 0; q < 32; ++q) s += sE1a[q].x;
            g_Kf[(d << 12) + 2048] = make_float2(0.5f * delta * s * sc + dsc, 0.0f);
        }

        // Two points per thread: l0p = part*512 + tid, l1p = l0p + 256
        int l0p = part * 512 + tid;
        int l1p = l0p + 256;
        float mtwo = __fdividef(-2.0f, delta);
        float s0_, c0_, s1_, c1_;
        sincospif((float)l0p * (1.0f / 4096.0f), &s0_, &c0_);
        sincospif((float)l1p * (1.0f / 4096.0f), &s1_, &c1_);
        float th0 = __fdividef(s0_, c0_);
        float th1 = __fdividef(s1_, c1_);
        float G0 = th0 * mtwo, G1 = th1 * mtwo;
        float Gsq0 = G0 * G0,  Gsq1 = G1 * G1;

        u64 P00a = 0ull, P01a = 0ull, P10a = 0ull, P11a = 0ull;
        u64 Q00a = 0ull, Q01a = 0ull, Q10a = 0ull, Q11a = 0ull;
        u64 P00b = 0ull, P01b = 0ull, P10b = 0ull, P11b = 0ull;
        u64 Q00b = 0ull, Q01b = 0ull, Q10b = 0ull, Q11b = 0ull;
        const ulonglong2* pE0a = (const ulonglong2*)sE0a;
        const ulonglong2* pE1a = (const ulonglong2*)sE1a;
        const ulonglong2* pE0b = (const ulonglong2*)sE0b;
        const ulonglong2* pE1b = (const ulonglong2*)sE1b;
        #pragma unroll 4
        for (int s = 0; s < 32; ++s) {
            float2 mn = sMN[s];
            ulonglong2 E0A = pE0a[s];
            ulonglong2 E1A = pE1a[s];
            ulonglong2 E0B = pE0b[s];
            ulonglong2 E1B = pE1b[s];
            // point 0
            {
                float dx  = mn.x - Gsq0;
                float dyn = mn.y * G0;
                float den = fmaf(dx, dx, dyn * dyn);
                float im  = __fdividef(1.0f, den);
                u64 t = pk2(dx * im, dyn * im);
                P00a = fma2(E0A.x, t, P00a); Q00a = fma2(E1A.x, t, Q00a);
                P01a = fma2(E0A.y, t, P01a); Q01a = fma2(E1A.y, t, Q01a);
                P10a = fma2(E0B.x, t, P10a); Q10a = fma2(E1B.x, t, Q10a);
                P11a = fma2(E0B.y, t, P11a); Q11a = fma2(E1B.y, t, Q11a);
            }
            // point 1
            {
                float dx  = mn.x - Gsq1;
                float dyn = mn.y * G1;
                float den = fmaf(dx, dx, dyn * dyn);
                float im  = __fdividef(1.0f, den);
                u64 t = pk2(dx * im, dyn * im);
                P00b = fma2(E0A.x, t, P00b); Q00b = fma2(E1A.x, t, Q00b);
                P01b = fma2(E0A.y, t, P01b); Q01b = fma2(E1A.y, t, Q01b);
                P10b = fma2(E0B.x, t, P10b); Q10b = fma2(E1B.x, t, Q10b);
                P11b = fma2(E0B.y, t, P11b); Q11b = fma2(E1B.y, t, Q11b);
            }
        }

        // epilogue per point: s = P + iG*Q, Woodbury, 2/u = 1 - i*th, scale
        #pragma unroll
        for (int k = 0; k < 2; ++k) {
            float G  = k ? G1 : G0;
            float th = k ? th1 : th0;
            int   l  = k ? l1p : l0p;
            u64 uP00 = k ? P00b : P00a, uQ00 = k ? Q00b : Q00a;
            u64 uP01 = k ? P01b : P01a, uQ01 = k ? Q01b : Q01a;
            u64 uP10 = k ? P10b : P10a, uQ10 = k ? Q10b : Q10a;
            u64 uP11 = k ? P11b : P11a, uQ11 = k ? Q11b : Q11a;
            float px, py, qx, qy;
            upk2(uP00, px, py); upk2(uQ00, qx, qy);
            float s00x = px - G * qy, s00y = py + G * qx;
            upk2(uP01, px, py); upk2(uQ01, qx, qy);
            float s01x = px - G * qy, s01y = py + G * qx;
            upk2(uP10, px, py); upk2(uQ10, qx, qy);
            float s10x = px - G * qy, s10y = py + G * qx;
            upk2(uP11, px, py); upk2(uQ11, qx, qy);
            float s11x = px - G * qy, s11y = py + G * qx;

            float nx  = s01x * s10x - s01y * s10y;
            float ny  = s01x * s10y + s01y * s10x;
            float dnx = 1.0f + s11x, dny = s11y;
            float ddi = __fdividef(1.0f, dnx * dnx + dny * dny);
            float cx  = (nx * dnx + ny * dny) * ddi;
            float cy  = (ny * dnx - nx * dny) * ddi;
            float k0x = s00x - cx, k0y = s00y - cy;
            float ax = k0x + th * k0y;
            float ay = k0y - th * k0x;
            ax = ax * sc + dsc; ay *= sc;
            if (l == 0) ay = 0.0f;
            g_Kf[(d << 12) + l] = make_float2(ax, ay);
            if (l > 0)
                g_Kf[(d << 12) + (NFFT - l)] = make_float2(ax, -ay);
        }
    } else if (blockIdx.x < 3072) {
        // -------- t1 path: 32d x 64l tiles, MLP=4 --------
        int m  = blockIdx.x - 1024;                // [0, 2048)
        int b4 = m >> 9;
        int lblk = (m >> 3) & 63;
        int dblk = m & 7;
        int d0 = dblk << 5, l0 = lblk << 6;
        const float4* x4 = (const float4*)x;
        float4 A[2], Bv[2];
        #pragma unroll
        for (int u = 0; u < 2; ++u) {
            int mm = tid + (u << 8);               // [0, 512)
            int l = mm >> 3, d4 = mm & 7;
            int base0 = ((b4 * NFFT) + l0 + l) * (DDIM / 4) + (d0 >> 2) + d4;
            A[u]  = x4[base0];
            Bv[u] = x4[base0 + 4 * NFFT * (DDIM / 4)];
        }
        #pragma unroll
        for (int u = 0; u < 2; ++u) {
            int mm = tid + (u << 8);
            int l = mm >> 3, d4 = mm & 7;
            tile[l][4 * d4 + 0] = make_float2(A[u].x, Bv[u].x);
            tile[l][4 * d4 + 1] = make_float2(A[u].y, Bv[u].y);
            tile[l][4 * d4 + 2] = make_float2(A[u].z, Bv[u].z);
            tile[l][4 * d4 + 3] = make_float2(A[u].w, Bv[u].w);
        }
        __syncthreads();
        float4* zT4 = (float4*)g_zT;
        #pragma unroll
        for (int u = 0; u < 4; ++u) {
            int mm = tid + (u << 8);               // [0, 1024)
            int dd = mm >> 5, lp = mm & 31;
            float2 t0 = tile[2 * lp][dd];
            float2 t1 = tile[2 * lp + 1][dd];
            zT4[(((b4 * DDIM) + d0 + dd) * NFFT + l0 + 2 * lp) >> 1]
                = make_float4(t0.x, t0.y, t1.x, t1.y);
        }
    } else {
        // -------- twiddle table (used by the NEXT launch only) --------
        int k = (blockIdx.x - 3072) * 256 + tid;
        double ang = -6.283185307179586476925286766559 * (double)k / (double)NFFT;
        g_tw[k] = make_float2((float)cos(ang), (float)sin(ang));
    }
}

// ---------------- radix-8 Stockham FFT, packed f32x2 butterflies ----------
__device__ __forceinline__ float2 cmulf(float2 a, float2 b) {
    return make_float2(a.x * b.x - a.y * b.y, a.x * b.y + a.y * b.x);
}
// scalar complex mul on packed value (unpack/repack are register-aliasing)
__device__ __forceinline__ u64 cmul_s(u64 a, float2 w) {
    float x, y; upk2(a, x, y);
    return pk2(x * w.x - y * w.y, x * w.y + y * w.x);
}
#define SWZ(m) ((m) ^ (((m) >> 4) & 7))

// Packed radix-8 butterfly (verified lane-by-lane vs scalar form)
template<int DIR>
__device__ __forceinline__ void bfly8(u64 a[8]) {
    const float S2 = 0.70710678118654752440f;
    const u64 NEG1 = pk2(-1.0f, -1.0f);
    const u64 S2S2 = pk2(S2, S2);
    const u64 J    = (DIR > 0) ? pk2(1.0f, -1.0f) : pk2(-1.0f, 1.0f);
    u64 b0 = add2(a[0], a[4]), c0 = fma2(a[4], NEG1, a[0]);
    u64 b1 = add2(a[1], a[5]), c1 = fma2(a[5], NEG1, a[1]);
    u64 b2 = add2(a[2], a[6]), c2 = fma2(a[6], NEG1, a[2]);
    u64 b3 = add2(a[3], a[7]), c3 = fma2(a[7], NEG1, a[3]);
    u64 tc1 = mul2(fma2(swp(c1), J, c1), S2S2);
    u64 tc2 = mul2(swp(c2), J);
    u64 tc3 = mul2(fma2(c3, NEG1, mul2(swp(c3), J)), S2S2);
    u64 p0 = add2(b0, b2), p1 = fma2(b2, NEG1, b0);
    u64 p2 = add2(b1, b3), p3 = fma2(b3, NEG1, b1);
    u64 q0 = add2(c0, tc2), q1 = fma2(tc2, NEG1, c0);
    u64 q2 = add2(tc1, tc3), q3 = fma2(tc3, NEG1, tc1);
    u64 jp3 = mul2(swp(p3), J);
    u64 jq3 = mul2(swp(q3), J);
    a[0] = add2(p0, p2);  a[4] = fma2(p2, NEG1, p0);
    a[2] = add2(p1, jp3); a[6] = fma2(jp3, NEG1, p1);
    a[1] = add2(q0, q2);  a[5] = fma2(q2, NEG1, q0);
    a[3] = add2(q1, jq3); a[7] = fma2(jq3, NEG1, q1);
}

// twiddle via single load + power chain (log depth): w^k, k=1..7
template<int DIR, int TSH>
__device__ __forceinline__ void stage_tw_store(u64* dst, u64 a[8], int i) {
    const int s = 1 << TSH;
    int ps = (i >> TSH) << TSH;
    if (TSH < 9) {
        float2 w1 = g_tw[ps];
        if (DIR < 0) w1.y = -w1.y;
        float2 w2 = cmulf(w1, w1);
        float2 w3 = cmulf(w2, w1);
        float2 w4 = cmulf(w2, w2);
        float2 w5 = cmulf(w3, w2);
        float2 w6 = cmulf(w3, w3);
        float2 w7 = cmulf(w4, w3);
        a[1] = cmul_s(a[1], w1);
        a[2] = cmul_s(a[2], w2);
        a[3] = cmul_s(a[3], w3);
        a[4] = cmul_s(a[4], w4);
        a[5] = cmul_s(a[5], w5);
        a[6] = cmul_s(a[6], w6);
        a[7] = cmul_s(a[7], w7);
    }
    int base = (i & (s - 1)) + (ps << 3);
    #pragma unroll
    for (int k = 0; k < 8; ++k) dst[SWZ(base + (k << TSH))] = a[k];
}

__global__ __launch_bounds__(512, 2) void fft_conv8_kernel() {
    extern __shared__ u64 sm64[];
    u64* S0 = sm64;
    u64* S1 = sm64 + NFFT;
    int d  = blockIdx.x & (DDIM - 1);
    int i  = threadIdx.x;
    // SWZ(i + j*512) == SWZ(i) + j*512 exactly (j*512 touches only bits >= 9,
    // SWZ XORs bits 4-6 into bits 0-2). One base register + immediate offsets.
    u64* L0 = S0 + SWZ(i);
    u64* L1 = S1 + SWZ(i);
    u64* sig = (u64*)g_zT + (size_t)blockIdx.x * NFFT;
    u64 a[8];

    // ---- forward ----
    #pragma unroll
    for (int j = 0; j < 8; ++j) a[j] = sig[i + j * 512];
    bfly8<1>(a); stage_tw_store<1, 0>(S0, a, i);
    __syncthreads();
    #pragma unroll
    for (int j = 0; j < 8; ++j) a[j] = L0[j * 512];
    bfly8<1>(a); stage_tw_store<1, 3>(S1, a, i);
    __syncthreads();
    #pragma unroll
    for (int j = 0; j < 8; ++j) a[j] = L1[j * 512];
    bfly8<1>(a); stage_tw_store<1, 6>(S0, a, i);
    __syncthreads();
    #pragma unroll
    for (int j = 0; j < 8; ++j) a[j] = L0[j * 512];
    bfly8<1>(a);
    // F3 (TSH=9): no twiddles; a[j] IS natural-order bin (i + j*512).
    {
        const float2* kf = g_Kf + (d << 12);
        #pragma unroll
        for (int j = 0; j < 8; ++j) a[j] = cmul_s(a[j], __ldg(&kf[i + j * 512]));
    }
    // ---- inverse ----
    bfly8<-1>(a); stage_tw_store<-1, 0>(S1, a, i);
    __syncthreads();
    #pragma unroll
    for (int j = 0; j < 8; ++j) a[j] = L1[j * 512];
    bfly8<-1>(a); stage_tw_store<-1, 3>(S0, a, i);
    __syncthreads();
    #pragma unroll
    for (int j = 0; j < 8; ++j) a[j] = L0[j * 512];
    bfly8<-1>(a); stage_tw_store<-1, 6>(S1, a, i);
    __syncthreads();
    #pragma unroll
    for (int j = 0; j < 8; ++j) a[j] = L1[j * 512];
    bfly8<-1>(a);
    #pragma unroll
    for (int k = 0; k < 8; ++k) sig[i + k * 512] = a[k];
}

// ---------------- untranspose + split Re/Im (32d x 64l tiles, MLP=4) --------
__global__ __launch_bounds__(256) void t2_kernel(float* __restrict__ y) {
    __shared__ float2 tile[32][65];
    int b4 = blockIdx.z;
    int d0 = blockIdx.x << 5;
    int l0 = blockIdx.y << 6;
    int tid = threadIdx.x;
    const float4* zT4 = (const float4*)g_zT;
    #pragma unroll
    for (int u = 0; u < 4; ++u) {
        int m = tid + (u << 8);
        int dd = m >> 5, lp = m & 31;
        float4 v = zT4[(((b4 * DDIM) + d0 + dd) * NFFT + l0 + 2 * lp) >> 1];
        tile[dd][2 * lp]     = make_float2(v.x, v.y);
        tile[dd][2 * lp + 1] = make_float2(v.z, v.w);
    }
    __syncthreads();
    float4* y4 = (float4*)y;
    #pragma unroll
    for (int u = 0; u < 4; ++u) {
        int m = tid + (u << 8);
        int k = m & 7, l = (m >> 3) & 63;
        int plane = m >> 9;                        // u<2 -> 0 (Re), u>=2 -> 1 (Im)
        float2 t0 = tile[4 * k + 0][l];
        float2 t1 = tile[4 * k + 1][l];
        float2 t2 = tile[4 * k + 2][l];
        float2 t3 = tile[4 * k + 3][l];
        int row = ((b4 + plane * 4) * NFFT + l0 + l) * (DDIM / 4) + (d0 >> 2) + k;
        y4[row] = plane ? make_float4(t0.y, t1.y, t2.y, t3.y)
                        : make_float4(t0.x, t1.x, t2.x, t3.x);
    }
}

// ---------------- launcher ----------------
extern "C" void kernel_launch(void* const* d_in, const int* in_sizes, int n_in,
                              void* d_out, int out_size) {
    const float*  x   = (const float*)d_in[0];
    const float2* lam = (const float2*)d_in[1];
    const float2* P   = (const float2*)d_in[2];
    const float2* B   = (const float2*)d_in[3];
    const float2* C   = (const float2*)d_in[4];
    const float*  Dp  = (const float*)d_in[5];
    const float*  ld  = (const float*)d_in[6];
    float* y = (float*)d_out;

    cudaFuncSetAttribute(fft_conv8_kernel,
                         cudaFuncAttributeMaxDynamicSharedMemorySize,
                         2 * NFFT * sizeof(u64));

    kf_t1_kernel<<<1024 + 2048 + 16, 256>>>(x, lam, P, B, C, ld, Dp);
    fft_conv8_kernel<<<NB4 * DDIM, 512, 2 * NFFT * sizeof(u64)>>>();
    t2_kernel<<<dim3(DDIM / 32, NFFT / 64, NB4), dim3(256)>>>(y);
}